// round 11
// baseline (speedup 1.0000x reference)
#include <cuda_runtime.h>

#define NPR      16384                 // values per row
#define NBINS    100
#define THREADS  256
#define WARPS    (THREADS / 32)        // 8
#define WARP_WORDS (NBINS * 32)        // 3200 words: hist[bin][lane], lane-private
#define SMEM_WORDS (WARPS * WARP_WORDS)// 25600 words = 102400 B
#define F4T      (NPR / (4 * THREADS)) // 16 float4 per thread (whole row staged)

// 2 CTAs/SM (smem-bound anyway) -> 128-reg budget so the 16x float4 staging
// (64 regs of data) survives ptxas: true MLP=16 per warp.
__global__ __launch_bounds__(THREADS, 2)
void hist_rows_kernel(const float* __restrict__ x, float* __restrict__ out)
{
    extern __shared__ int hist[];      // [WARPS][NBINS][32], dynamic 102.4 KB

    const int tid  = threadIdx.x;
    const int lane = tid & 31;
    // Lane-private counter base: bank == lane for every access -> zero
    // bank conflicts, zero races, no atomics at all.
    int* h = &hist[(tid >> 5) * WARP_WORDS + lane];

    const float4* p =
        reinterpret_cast<const float4*>(x) + (size_t)blockIdx.x * (NPR / 4) + tid;

    // Stage the ENTIRE row slice first: 16 independent LDG.128 per thread.
    // First DRAM latency hides under the smem zero-loop + barrier.
    float4 v[F4T];
    #pragma unroll
    for (int j = 0; j < F4T; j++)
        v[j] = __ldcs(p + j * THREADS);

    #pragma unroll
    for (int i = tid; i < SMEM_WORDS; i += THREADS)
        hist[i] = 0;
    __syncthreads();

    // Drain: plain increments into lane-private counters.
    // Exact ref semantics: floor(100*trunc(x)/256) == (xi*100)>>8
    // (100*xi < 2^16 exactly representable; /256 is a power of two).
    #pragma unroll
    for (int j = 0; j < F4T; j++) {
        h[((((int)v[j].x * NBINS) >> 8) << 5)]++;
        h[((((int)v[j].y * NBINS) >> 8) << 5)]++;
        h[((((int)v[j].z * NBINS) >> 8) << 5)]++;
        h[((((int)v[j].w * NBINS) >> 8) << 5)]++;
    }
    __syncthreads();

    // Reduce 256 lane-counters per bin. Lane-rotated index keeps the
    // 32 reading lanes of each warp on 32 distinct banks every step.
    if (tid < NBINS) {
        int s = 0;
        #pragma unroll 8
        for (int i = 0; i < THREADS; i++) {
            int w = i >> 5;
            int l = (i + tid) & 31;
            s += hist[w * WARP_WORDS + (tid << 5) + l];
        }
        __stwt(&out[(size_t)blockIdx.x * NBINS + tid], (float)s);
    }
}

extern "C" void kernel_launch(void* const* d_in, const int* in_sizes, int n_in,
                              void* d_out, int out_size)
{
    const float* x = (const float*)d_in[0];
    float* out = (float*)d_out;
    const int rows = out_size / NBINS;   // 4096

    // Dynamic smem above 48 KB needs an explicit opt-in. Host-side attribute
    // set, no allocation, executes immediately (not a captured stream op) —
    // deterministic on every call.
    cudaFuncSetAttribute(hist_rows_kernel,
                         cudaFuncAttributeMaxDynamicSharedMemorySize,
                         SMEM_WORDS * sizeof(int));

    hist_rows_kernel<<<rows, THREADS, SMEM_WORDS * sizeof(int)>>>(x, out);
}

// round 13
// speedup vs baseline: 2.4956x; 2.4956x over previous
#include <cuda_runtime.h>

#define NPR     16384            // values per row
#define NBINS   100
#define THREADS 256
#define NSUB    (THREADS / 16)   // 16 half-warp sub-histograms
#define HSTRIDE 104              // padded stride (104 % 32 == 8 -> bank shift between regions)
#define F4_PER_THREAD (NPR / (4 * THREADS))  // 16
#define BATCH   8                // float4 per staged batch

// Best measured configuration (45.12 us, ~6.35 TB/s = LTS chip cap).
// Default occupancy: ptxas keeps regs=32, occ ~94%; cross-warp parallelism
// (60 warps/SM) covers DRAM latency better than any explicit-MLP variant.
__global__ __launch_bounds__(THREADS)
void hist_rows_kernel(const float* __restrict__ x, float* __restrict__ out)
{
    __shared__ int hist[NSUB * HSTRIDE];

    const int tid = threadIdx.x;

    #pragma unroll
    for (int i = tid; i < NSUB * HSTRIDE; i += THREADS)
        hist[i] = 0;
    __syncthreads();

    // Half-warp-private histogram region: lanes 0-15 / 16-31 of each warp
    // use separate sub-histograms -> ~2x fewer same-address ATOMS collisions.
    int* h = &hist[(tid >> 4) * HSTRIDE];

    const float4* row =
        reinterpret_cast<const float4*>(x) + (size_t)blockIdx.x * (NPR / 4);

    #pragma unroll
    for (int outer = 0; outer < F4_PER_THREAD / BATCH; outer++) {
        // Stage a batch of independent LDG.128 (streaming: data read once)
        float4 v[BATCH];
        #pragma unroll
        for (int j = 0; j < BATCH; j++)
            v[j] = __ldcs(&row[(outer * BATCH + j) * THREADS + tid]);

        // Drain into shared atomics (no-return ATOMS: RMW in the LSU pipe,
        // no scoreboard round-trip).
        // Exact ref semantics: trunc->int, then floor(100*xi/256) == (xi*100)>>8
        // (100*xi < 2^16 exactly representable; /256 is a power of two).
        #pragma unroll
        for (int j = 0; j < BATCH; j++) {
            atomicAdd(&h[((int)v[j].x * NBINS) >> 8], 1);
            atomicAdd(&h[((int)v[j].y * NBINS) >> 8], 1);
            atomicAdd(&h[((int)v[j].z * NBINS) >> 8], 1);
            atomicAdd(&h[((int)v[j].w * NBINS) >> 8], 1);
        }
    }
    __syncthreads();

    // Reduce 16 sub-histograms and emit float counts
    for (int b = tid; b < NBINS; b += THREADS) {
        int s = 0;
        #pragma unroll
        for (int w = 0; w < NSUB; w++)
            s += hist[w * HSTRIDE + b];
        out[(size_t)blockIdx.x * NBINS + b] = (float)s;
    }
}

extern "C" void kernel_launch(void* const* d_in, const int* in_sizes, int n_in,
                              void* d_out, int out_size)
{
    const float* x = (const float*)d_in[0];
    float* out = (float*)d_out;
    const int rows = out_size / NBINS;   // 4096
    hist_rows_kernel<<<rows, THREADS>>>(x, out);
}